// round 5
// baseline (speedup 1.0000x reference)
#include <cuda_runtime.h>
#include <cstdint>

// Bayer mosaic channel select:
//   out[b,i,j] = img[b, c, i, j]
//   c = 1 if (i+j) even; else 2 if i even; else 0
// Row-parity view:
//   i even: j even -> ch1, j odd -> ch2
//   i odd : j even -> ch0, j odd -> ch1
//
// Persistent grid-stride kernel: exactly one resident wave
// (148 SMs x 8 CTAs x 256 thr), each iteration does the R1 access pattern
// (one LDG.128 per plane, one STG.128). Unroll 4 -> 8 independent in-flight
// loads per thread at grid-stride-separated addresses (no intra-thread
// adjacent-sector serialization, unlike R2).

static constexpr int C = 3;
static constexpr int H = 2048;
static constexpr int W = 2048;
static constexpr int BATCH = 8;
static constexpr int64_t TOTAL4 = (int64_t)BATCH * H * (W / 4);  // 8,388,608

__global__ __launch_bounds__(256)
void bayer_kernel(const float* __restrict__ img, float* __restrict__ out) {
    const int W4 = W / 4;                       // 512 float4 per row (power of 2)
    const int64_t stride = (int64_t)gridDim.x * blockDim.x;
    int64_t gid = (int64_t)blockIdx.x * blockDim.x + threadIdx.x;

    #pragma unroll 4
    for (; gid < TOTAL4; gid += stride) {
        // power-of-two split: j4 = gid & 511, bi = gid >> 9
        const int j4 = (int)(gid & (W4 - 1));
        const int64_t bi = gid >> 9;            // b*H + i
        const int i = (int)(bi & (H - 1));
        const int b = (int)(bi >> 11);

        int cA, cB;                             // cA: even j, cB: odd j
        if ((i & 1) == 0) { cA = 1; cB = 2; }
        else              { cA = 0; cB = 1; }

        const int64_t plane = (int64_t)H * W;
        const int64_t row_base = (int64_t)b * C * plane + (int64_t)i * W + (int64_t)j4 * 4;

        const float4 a  = *reinterpret_cast<const float4*>(img + row_base + (int64_t)cA * plane);
        const float4 bv = *reinterpret_cast<const float4*>(img + row_base + (int64_t)cB * plane);

        float4 o;
        o.x = a.x;   // even j
        o.y = bv.y;  // odd j
        o.z = a.z;   // even j
        o.w = bv.w;  // odd j

        *reinterpret_cast<float4*>(out + bi * W + (int64_t)j4 * 4) = o;
    }
}

extern "C" void kernel_launch(void* const* d_in, const int* in_sizes, int n_in,
                              void* d_out, int out_size) {
    const float* img = (const float*)d_in[0];
    float* out = (float*)d_out;

    // One full resident wave: 152 SMs on GB300, 8 CTAs/SM at 256thr/16regs.
    const int blocks = 152 * 8;   // 1216 CTAs
    bayer_kernel<<<blocks, 256>>>(img, out);
}

// round 6
// speedup vs baseline: 1.0895x; 1.0895x over previous
#include <cuda_runtime.h>
#include <cstdint>

// Bayer mosaic channel select:
//   out[b,i,j] = img[b, c, i, j]
//   c = 1 if (i+j) even; else 2 if i even; else 0
// Row-parity view:
//   i even: j even -> ch1, j odd -> ch2
//   i odd : j even -> ch0, j odd -> ch1
//
// One CTA per image row: block=512 threads, each thread one float4 (4 j's).
// Per CTA: two contiguous 8KB read extents (the two relevant channel rows)
// and one contiguous 8KB write extent -> maximal DRAM open-row / L2-slice
// locality. Per-thread instruction shape identical to the best (R1) kernel:
// 2x LDG.128 + 1x STG.128, no unroll, no div/mod.

static constexpr int C = 3;
static constexpr int H = 2048;
static constexpr int W = 2048;

__global__ __launch_bounds__(512)
void bayer_kernel(const float* __restrict__ img, float* __restrict__ out) {
    const int j4 = threadIdx.x;          // [0,512): float4 index within row
    const int i  = blockIdx.x;           // row
    const int b  = blockIdx.y;           // batch

    // Channels for this row: cA serves even j, cB serves odd j
    int cA, cB;
    if ((i & 1) == 0) { cA = 1; cB = 2; }
    else              { cA = 0; cB = 1; }

    const int64_t plane = (int64_t)H * W;
    const int64_t row_base = (int64_t)b * C * plane + (int64_t)i * W + (int64_t)j4 * 4;

    const float4 a  = *reinterpret_cast<const float4*>(img + row_base + (int64_t)cA * plane);
    const float4 bv = *reinterpret_cast<const float4*>(img + row_base + (int64_t)cB * plane);

    float4 o;
    o.x = a.x;   // even j
    o.y = bv.y;  // odd j
    o.z = a.z;   // even j
    o.w = bv.w;  // odd j

    const int64_t out_idx = ((int64_t)b * H + i) * W + (int64_t)j4 * 4;
    *reinterpret_cast<float4*>(out + out_idx) = o;
}

extern "C" void kernel_launch(void* const* d_in, const int* in_sizes, int n_in,
                              void* d_out, int out_size) {
    const float* img = (const float*)d_in[0];
    float* out = (float*)d_out;

    dim3 grid(H, 8);     // (2048 rows, 8 batches) = 16384 CTAs of 512 threads
    bayer_kernel<<<grid, 512>>>(img, out);
}